// round 14
// baseline (speedup 1.0000x reference)
#include <cuda_runtime.h>
#include <cuda_fp16.h>
#include <cstdint>

// Problem constants
#define B_   8
#define K_   1024
#define N_   (B_ * K_)
#define S_   64
#define T_   65536
#define CIN  64
#define COUT 64
#define CKS  128
#define HID_ 32
#define ZDIM 128
#define RTOT (CKS * COUT)

// Device scratch
__device__ __half g_h1h[N_ * HID_];              // fp16 [n][j]
__device__ float  g_bias[N_ * COUT];
__device__ __half g_weight[(size_t)N_ * RTOT];   // fp16 [n][r], r = c*64+o

// ---------------------------------------------------------------------------
// PTX helpers
// ---------------------------------------------------------------------------
__device__ __forceinline__ uint32_t smem_u32(const void* p) {
    uint32_t a;
    asm("{ .reg .u64 t; cvta.to.shared.u64 t, %1; cvt.u32.u64 %0, t; }" : "=r"(a) : "l"(p));
    return a;
}
#define LDSM_X4(r0,r1,r2,r3,addr) \
    asm volatile("ldmatrix.sync.aligned.m8n8.x4.shared.b16 {%0,%1,%2,%3}, [%4];" \
        : "=r"(r0),"=r"(r1),"=r"(r2),"=r"(r3) : "r"(addr))
#define LDSM_X2(r0,r1,addr) \
    asm volatile("ldmatrix.sync.aligned.m8n8.x2.shared.b16 {%0,%1}, [%2];" \
        : "=r"(r0),"=r"(r1) : "r"(addr))
#define LDSM_X2T(r0,r1,addr) \
    asm volatile("ldmatrix.sync.aligned.m8n8.x2.trans.shared.b16 {%0,%1}, [%2];" \
        : "=r"(r0),"=r"(r1) : "r"(addr))
#define MMA16816F(d,a0,a1,a2,a3,b0,b1) \
    asm volatile("mma.sync.aligned.m16n8k16.row.col.f32.f16.f16.f32 " \
        "{%0,%1,%2,%3}, {%4,%5,%6,%7}, {%8,%9}, {%0,%1,%2,%3};" \
        : "+f"((d)[0]),"+f"((d)[1]),"+f"((d)[2]),"+f"((d)[3]) \
        : "r"(a0),"r"(a1),"r"(a2),"r"(a3),"r"(b0),"r"(b1))

#define CPA16(saddr, gptr) \
    asm volatile("cp.async.cg.shared.global [%0], [%1], 16;" \
        :: "r"(saddr), "l"(gptr) : "memory")
#define CPA_COMMIT() asm volatile("cp.async.commit_group;" ::: "memory")
#define CPA_WAIT0()  asm volatile("cp.async.wait_group 0;" ::: "memory")

__device__ __forceinline__ void sts64(uint32_t addr, uint32_t a, uint32_t b) {
    asm volatile("st.shared.v2.b32 [%0], {%1,%2};" :: "r"(addr), "r"(a), "r"(b));
}
__device__ __forceinline__ uint32_t h2u(__half2 h) {
    return *reinterpret_cast<uint32_t*>(&h);
}

// ---------------------------------------------------------------------------
// Kernel 1: hyper MLP heads — split grid (64 ktiles x 8 b), 16 kk per CTA.
// h1 and h3 computed in parallel by thread halves; z operand is warp-broadcast.
// ---------------------------------------------------------------------------
__global__ __launch_bounds__(256) void hyper_kernel(
    const float* __restrict__ z,
    const float* __restrict__ w1, const float* __restrict__ b1,
    const float* __restrict__ w3, const float* __restrict__ b3,
    const float* __restrict__ w4, const float* __restrict__ b4)
{
    extern __shared__ float hs[];
    float* zs   = hs;            // [j][kk] 128x16      = 2048
    float* w1sT = hs + 2048;     // [j][jo] 128x33      = 4224
    float* w3sT = hs + 6272;     //                       4224
    float* w4sT = hs + 10496;    // [j][o]  32x65       = 2080
    float* h3s  = hs + 12576;    // [kk][jo] 16x33      = 528

    const int b  = blockIdx.y;
    const int k0 = blockIdx.x * 16;
    const int tid = threadIdx.x;

    // z tile: 2048 elems
    #pragma unroll
    for (int i = 0; i < 8; ++i) {
        int f = i * 256 + tid;
        zs[f] = z[((size_t)(b * ZDIM + (f >> 4))) * K_ + k0 + (f & 15)];
    }
    #pragma unroll
    for (int i = 0; i < 16; ++i) {
        int f = i * 256 + tid;
        w1sT[(f & 127) * 33 + (f >> 7)] = w1[f];
    }
    #pragma unroll
    for (int i = 0; i < 16; ++i) {
        int f = i * 256 + tid;
        w3sT[(f & 127) * 33 + (f >> 7)] = w3[f];
    }
    #pragma unroll
    for (int i = 0; i < 8; ++i) {
        int f = i * 256 + tid;
        w4sT[(f & 31) * 65 + (f >> 5)] = w4[f];
    }
    __syncthreads();

    // h1 (threads 0-127) / h3 (threads 128-255), each thread 4 kk
    {
        const int half = tid >> 7;           // 0: h1, 1: h3
        const int jo   = tid & 31;
        const int kkg  = (tid >> 5) & 3;     // 0..3 -> kk block of 4
        const float* wT = half ? w3sT : w1sT;
        const float  bb = half ? b3[jo] : b1[jo];
        float a[4] = {bb, bb, bb, bb};
        #pragma unroll 8
        for (int j = 0; j < ZDIM; ++j) {
            float4 zv = *(const float4*)(zs + j * 16 + kkg * 4);   // warp broadcast
            float w = wT[j * 33 + jo];
            a[0] += w * zv.x; a[1] += w * zv.y; a[2] += w * zv.z; a[3] += w * zv.w;
        }
        #pragma unroll
        for (int u = 0; u < 4; ++u) {
            int kk = kkg * 4 + u;
            float r = fmaxf(a[u], 0.f);
            if (!half)
                g_h1h[(size_t)(b * K_ + k0 + kk) * HID_ + jo] = __float2half(r);
            else
                h3s[kk * 33 + jo] = r;
        }
    }
    __syncthreads();

    // bias: 64 o x 16 kk, thread = (o, kg) with 4 kk each
    {
        const int o  = tid & 63;
        const int kg = tid >> 6;             // 0..3
        float ab[4];
        float bv = b4[o];
        #pragma unroll
        for (int u = 0; u < 4; ++u) ab[u] = bv;
        #pragma unroll
        for (int j = 0; j < HID_; ++j) {
            float w = w4sT[j * 65 + o];
            #pragma unroll
            for (int u = 0; u < 4; ++u)
                ab[u] += w * h3s[(kg * 4 + u) * 33 + j];
        }
        #pragma unroll
        for (int u = 0; u < 4; ++u)
            g_bias[(size_t)(b * K_ + k0 + kg * 4 + u) * COUT + o] = ab[u];
    }
}
#define HYPER_SMEM ((12576 + 528) * 4)   // 52416 B

// ---------------------------------------------------------------------------
// Kernel 2: weight-gen via mma.sync fp16 (proven R10/R11)
// ---------------------------------------------------------------------------
#define D_STR 136

__global__ __launch_bounds__(256) void wgen_kernel(
    const float* __restrict__ w2, const float* __restrict__ b2)
{
    __shared__ __align__(16) char wsm[128 * D_STR * 2];
    __half* Ah = (__half*)wsm;
    __half* Bh = (__half*)(wsm + 10240);

    const int rtile = blockIdx.x;
    const int ntile = blockIdx.y;
    const int tid  = threadIdx.x;
    const int wid  = tid >> 5;
    const int lane = tid & 31;

    const uint4* hsrc = (const uint4*)(g_h1h + (size_t)ntile * 128 * HID_);
    #pragma unroll
    for (int i = 0; i < 2; ++i) {
        int q = i * 256 + tid;
        int n = q >> 2, jq = q & 3;
        *(uint4*)&Ah[n * 40 + jq * 8] = __ldg(hsrc + q);
    }
    const float4* wsrc = (const float4*)(w2 + (size_t)rtile * 128 * HID_);
    #pragma unroll
    for (int i = 0; i < 4; ++i) {
        int q = i * 256 + tid;
        int r = q >> 3, jq = q & 7;
        float4 v = __ldg(wsrc + q);
        uint32_t p0 = h2u(__floats2half2_rn(v.x, v.y));
        uint32_t p1 = h2u(__floats2half2_rn(v.z, v.w));
        sts64(smem_u32(&Bh[r * 40 + jq * 4]), p0, p1);
    }
    __syncthreads();

    const uint32_t sbA = smem_u32(Ah);
    const uint32_t sbB = smem_u32(Bh);
    const int nb = (wid & 1) * 64;
    const int rb = (wid >> 1) * 32;

    float acc[4][4][4];
    #pragma unroll
    for (int mt = 0; mt < 4; ++mt)
        #pragma unroll
        for (int nt = 0; nt < 4; ++nt)
            #pragma unroll
            for (int u = 0; u < 4; ++u) acc[mt][nt][u] = 0.f;

    const int a_row = lane & 15;
    const int a_kh  = lane >> 4;
    const int b_row = lane & 7;
    const int b_ks  = (lane >> 3) & 1;

    #pragma unroll
    for (int ks = 0; ks < 2; ++ks) {
        const int k0 = ks * 16;
        uint32_t a[4][4];
        #pragma unroll
        for (int mt = 0; mt < 4; ++mt) {
            uint32_t addr = sbA + (nb + mt * 16 + a_row) * 80 + (k0 + a_kh * 8) * 2;
            LDSM_X4(a[mt][0], a[mt][1], a[mt][2], a[mt][3], addr);
        }
        uint32_t bf[4][2];
        #pragma unroll
        for (int nt = 0; nt < 4; ++nt) {
            uint32_t addr = sbB + (rb + nt * 8 + b_row) * 80 + (k0 + b_ks * 8) * 2;
            LDSM_X2(bf[nt][0], bf[nt][1], addr);
        }
        #pragma unroll
        for (int mt = 0; mt < 4; ++mt)
            #pragma unroll
            for (int nt = 0; nt < 4; ++nt)
                MMA16816F(acc[mt][nt], a[mt][0], a[mt][1], a[mt][2], a[mt][3],
                          bf[nt][0], bf[nt][1]);
    }

    __syncthreads();
    __half* D = (__half*)wsm;
    const int g   = lane >> 2;
    const int tig = lane & 3;
    #pragma unroll
    for (int nt = 0; nt < 4; ++nt) {
        const int rl = rb + nt * 8 + tig * 2;
        const int r  = rtile * 128 + rl;
        const float bv0 = __ldg(b2 + r);
        const float bv1 = __ldg(b2 + r + 1);
        #pragma unroll
        for (int mt = 0; mt < 4; ++mt) {
            const int n0 = nb + mt * 16 + g;
            *(__half2*)(D + n0 * D_STR + rl) =
                __floats2half2_rn(acc[mt][nt][0] + bv0, acc[mt][nt][1] + bv1);
            *(__half2*)(D + (n0 + 8) * D_STR + rl) =
                __floats2half2_rn(acc[mt][nt][2] + bv0, acc[mt][nt][3] + bv1);
        }
    }
    __syncthreads();

    #pragma unroll
    for (int i = 0; i < 8; ++i) {
        int q = i * 256 + tid;
        int row = q >> 4, col = (q & 15) * 8;
        uint4 v = *(const uint4*)(D + row * D_STR + col);
        *(uint4*)(g_weight + (size_t)(ntile * 128 + row) * RTOT + rtile * 128 + col) = v;
    }
}

// ---------------------------------------------------------------------------
// Kernel 3: main GEMM via mma.sync fp16 — R11 layout (best measured).
// Region0 [0,18432): x fp32 staging(17408)+P(1024) -> B fp16 [c][o] 144B rows
//                    -> out fp32 staging [o][72f] 288B rows.
// Region1 [18432, 29872): A fp16 [sp][ch] 176B rows.
// ---------------------------------------------------------------------------
#define P_OFF   17408u
#define A_OFF   18432u
#define A_STR   176
#define O_STRF  72
#define SM_MAIN (18432 + 65 * 176)   // 29872 B

__global__ __launch_bounds__(128, 6) void main_mma_kernel(
    const float* __restrict__ x, float* __restrict__ out)
{
    extern __shared__ __align__(1024) char smem[];
    const uint32_t sb = smem_u32(smem);
    const int tid  = threadIdx.x;
    const int wid  = tid >> 5;
    const int lane = tid & 31;
    const int n  = (N_ - 1) - blockIdx.x;
    const int b  = n >> 10;
    const int t0 = (n & 1023) * 64;

    const float* xb = x + (size_t)b * CIN * T_ + t0;
    float* Xs = (float*)smem;                 // [ch][s], stride 68 floats
    float* P  = (float*)(smem + P_OFF);

    // phase 0: x -> staging via cp.async
    #pragma unroll
    for (int i = 0; i < 8; ++i) {
        int f = i * 128 + tid;
        int ch = f >> 4, sc = (f & 15) * 4;
        CPA16(sb + (uint32_t)(ch * 68 + sc) * 4, xb + (size_t)ch * T_ + sc);
    }
    if (tid < 64) P[tid] = t0 ? __ldg(xb + (size_t)tid * T_ - 1) : 0.f;
    CPA_COMMIT();
    CPA_WAIT0();
    __syncthreads();

    // phase 1: A-build (fp16 [sp][ch], rows 0..64)
    if (tid < 16) {
        float4 p = *(const float4*)(P + tid * 4);
        sts64(sb + A_OFF + tid * 8,
              h2u(__floats2half2_rn(p.x, p.y)), h2u(__floats2half2_rn(p.z, p.w)));
    }
    #pragma unroll
    for (int i = 0; i < 8; ++i) {
        int idx = i * 128 + tid;
        int sp  = (idx & 63) + 1;
        int chg = idx >> 6;
        const float* xs = Xs + chg * 4 * 68 + (sp - 1);
        float e0 = xs[0], e1 = xs[68], e2 = xs[136], e3 = xs[204];
        sts64(sb + A_OFF + sp * A_STR + chg * 8,
              h2u(__floats2half2_rn(e0, e1)), h2u(__floats2half2_rn(e2, e3)));
    }
    __syncthreads();   // staging fully consumed -> region0 reusable as B

    // phase 2: W -> B (region0) via cp.async, [c][o] rows 144B
    {
        const uint4* wsrc = (const uint4*)(g_weight + (size_t)n * RTOT);
        #pragma unroll
        for (int i = 0; i < 8; ++i) {
            int f4 = i * 128 + tid;
            int c = f4 >> 3, o0 = (f4 & 7) * 8;
            CPA16(sb + (uint32_t)(c * 144 + o0 * 2), wsrc + f4);
        }
        CPA_COMMIT();
        CPA_WAIT0();
    }
    __syncthreads();

    // phase 3: MMA mainloop
    const int s_base = (wid & 1) * 32;
    const int o_base = (wid >> 1) * 32;

    float acc[2][4][4];
    #pragma unroll
    for (int mt = 0; mt < 2; ++mt)
        #pragma unroll
        for (int nt = 0; nt < 4; ++nt)
            #pragma unroll
            for (int r = 0; r < 4; ++r) acc[mt][nt][r] = 0.f;

    const uint32_t a_row = lane & 15;
    const uint32_t a_kh  = lane >> 4;
    const uint32_t b_kr  = lane & 15;

    #pragma unroll
    for (int k = 0; k < 8; ++k) {
        const int rowoff = (k < 4) ? 1 : 0;
        const int chcol  = (k & 3) * 16;
        uint32_t a[2][4];
        #pragma unroll
        for (int mt = 0; mt < 2; ++mt) {
            uint32_t addr = sb + A_OFF
                          + (rowoff + s_base + mt * 16 + a_row) * A_STR
                          + (chcol + a_kh * 8) * 2;
            LDSM_X4(a[mt][0], a[mt][1], a[mt][2], a[mt][3], addr);
        }
        uint32_t bf[4][2];
        #pragma unroll
        for (int nt = 0; nt < 4; ++nt) {
            uint32_t addr = sb + (k * 16 + b_kr) * 144 + (o_base + nt * 8) * 2;
            LDSM_X2T(bf[nt][0], bf[nt][1], addr);
        }
        #pragma unroll
        for (int mt = 0; mt < 2; ++mt)
            #pragma unroll
            for (int nt = 0; nt < 4; ++nt)
                MMA16816F(acc[mt][nt], a[mt][0], a[mt][1], a[mt][2], a[mt][3],
                          bf[nt][0], bf[nt][1]);
    }
    __syncthreads();   // all LDSM done -> region0 reusable as out staging

    // phase 4: epilogue — frags + bias -> smem [o][s], then coalesced stores
    {
        float* D = (float*)smem;             // [64 o][O_STRF]
        const int g   = lane >> 2;
        const int tig = lane & 3;
        #pragma unroll
        for (int nt = 0; nt < 4; ++nt) {
            const int o = o_base + nt * 8 + 2 * tig;
            const float bv0 = __ldg(g_bias + (size_t)n * COUT + o);
            const float bv1 = __ldg(g_bias + (size_t)n * COUT + o + 1);
            #pragma unroll
            for (int mt = 0; mt < 2; ++mt) {
                const int s = s_base + mt * 16 + g;
                D[o * O_STRF + s]           = acc[mt][nt][0] + bv0;
                D[(o + 1) * O_STRF + s]     = acc[mt][nt][1] + bv1;
                D[o * O_STRF + s + 8]       = acc[mt][nt][2] + bv0;
                D[(o + 1) * O_STRF + s + 8] = acc[mt][nt][3] + bv1;
            }
        }
        __syncthreads();

        float* ob = out + (size_t)b * COUT * T_ + t0;
        #pragma unroll
        for (int i = 0; i < 8; ++i) {
            int q = i * 128 + tid;
            int row = q >> 4, col = (q & 15) * 4;
            float4 v = *(const float4*)(D + row * O_STRF + col);
            *(float4*)(ob + (size_t)row * T_ + col) = v;
        }
    }
}

// ---------------------------------------------------------------------------
extern "C" void kernel_launch(void* const* d_in, const int* in_sizes, int n_in,
                              void* d_out, int out_size)
{
    const float* x  = (const float*)d_in[0];
    const float* z  = (const float*)d_in[1];
    const float* w1 = (const float*)d_in[2];
    const float* b1 = (const float*)d_in[3];
    const float* w2 = (const float*)d_in[4];
    const float* b2 = (const float*)d_in[5];
    const float* w3 = (const float*)d_in[6];
    const float* b3 = (const float*)d_in[7];
    const float* w4 = (const float*)d_in[8];
    const float* b4 = (const float*)d_in[9];
    float* out = (float*)d_out;

    cudaFuncSetAttribute(hyper_kernel,    cudaFuncAttributeMaxDynamicSharedMemorySize, HYPER_SMEM);
    cudaFuncSetAttribute(main_mma_kernel, cudaFuncAttributeMaxDynamicSharedMemorySize, SM_MAIN);

    hyper_kernel<<<dim3(64, 8), 256, HYPER_SMEM>>>(z, w1, b1, w3, b3, w4, b4);
    wgen_kernel<<<dim3(64, 64), 256>>>(w2, b2);
    main_mma_kernel<<<N_, 128, SM_MAIN>>>(x, out);
}

// round 15
// speedup vs baseline: 1.5042x; 1.5042x over previous
#include <cuda_runtime.h>
#include <cuda_fp16.h>
#include <cstdint>

// Problem constants
#define B_   8
#define K_   1024
#define N_   (B_ * K_)
#define S_   64
#define T_   65536
#define CIN  64
#define COUT 64
#define CKS  128
#define HID_ 32
#define ZDIM 128
#define RTOT (CKS * COUT)

// Device scratch
__device__ __half g_h1h[N_ * HID_];              // fp16 [n][j]
__device__ float  g_bias[N_ * COUT];
__device__ __half g_weight[(size_t)N_ * RTOT];   // fp16 [n][r], r = c*64+o

// ---------------------------------------------------------------------------
// PTX helpers
// ---------------------------------------------------------------------------
__device__ __forceinline__ uint32_t smem_u32(const void* p) {
    uint32_t a;
    asm("{ .reg .u64 t; cvta.to.shared.u64 t, %1; cvt.u32.u64 %0, t; }" : "=r"(a) : "l"(p));
    return a;
}
#define LDSM_X4(r0,r1,r2,r3,addr) \
    asm volatile("ldmatrix.sync.aligned.m8n8.x4.shared.b16 {%0,%1,%2,%3}, [%4];" \
        : "=r"(r0),"=r"(r1),"=r"(r2),"=r"(r3) : "r"(addr))
#define LDSM_X2(r0,r1,addr) \
    asm volatile("ldmatrix.sync.aligned.m8n8.x2.shared.b16 {%0,%1}, [%2];" \
        : "=r"(r0),"=r"(r1) : "r"(addr))
#define LDSM_X2T(r0,r1,addr) \
    asm volatile("ldmatrix.sync.aligned.m8n8.x2.trans.shared.b16 {%0,%1}, [%2];" \
        : "=r"(r0),"=r"(r1) : "r"(addr))
#define MMA16816F(d,a0,a1,a2,a3,b0,b1) \
    asm volatile("mma.sync.aligned.m16n8k16.row.col.f32.f16.f16.f32 " \
        "{%0,%1,%2,%3}, {%4,%5,%6,%7}, {%8,%9}, {%0,%1,%2,%3};" \
        : "+f"((d)[0]),"+f"((d)[1]),"+f"((d)[2]),"+f"((d)[3]) \
        : "r"(a0),"r"(a1),"r"(a2),"r"(a3),"r"(b0),"r"(b1))

#define CPA16(saddr, gptr) \
    asm volatile("cp.async.cg.shared.global [%0], [%1], 16;" \
        :: "r"(saddr), "l"(gptr) : "memory")
#define CPA_COMMIT() asm volatile("cp.async.commit_group;" ::: "memory")
#define CPA_WAIT0()  asm volatile("cp.async.wait_group 0;" ::: "memory")

__device__ __forceinline__ void sts64(uint32_t addr, uint32_t a, uint32_t b) {
    asm volatile("st.shared.v2.b32 [%0], {%1,%2};" :: "r"(addr), "r"(a), "r"(b));
}
__device__ __forceinline__ uint32_t h2u(__half2 h) {
    return *reinterpret_cast<uint32_t*>(&h);
}

// ---------------------------------------------------------------------------
// Kernel 1: hyper MLP heads — register-blocked, grid (32,8) (proven 12.2us)
// ---------------------------------------------------------------------------
__global__ __launch_bounds__(256) void hyper_kernel(
    const float* __restrict__ z,
    const float* __restrict__ w1, const float* __restrict__ b1,
    const float* __restrict__ w3, const float* __restrict__ b3,
    const float* __restrict__ w4, const float* __restrict__ b4)
{
    extern __shared__ float hs[];
    float* zs   = hs;            // [j][kk] 128x32
    float* w1sT = hs + 4096;     // [j][jo] 128x33
    float* w3sT = hs + 8320;
    float* w4sT = hs + 12544;    // [j][o]  32x65
    float* h3s  = hs + 14624;    // [kk][jo] 32x33

    const int b  = blockIdx.y;
    const int k0 = blockIdx.x * 32;
    const int tid = threadIdx.x;

    #pragma unroll
    for (int i = 0; i < 16; ++i) {
        int f = i * 256 + tid;
        zs[f] = z[((size_t)(b * ZDIM + (f >> 5))) * K_ + k0 + (f & 31)];
    }
    #pragma unroll
    for (int i = 0; i < 16; ++i) {
        int f = i * 256 + tid;
        w1sT[(f & 127) * 33 + (f >> 7)] = w1[f];
    }
    #pragma unroll
    for (int i = 0; i < 16; ++i) {
        int f = i * 256 + tid;
        w3sT[(f & 127) * 33 + (f >> 7)] = w3[f];
    }
    #pragma unroll
    for (int i = 0; i < 8; ++i) {
        int f = i * 256 + tid;
        w4sT[(f & 31) * 65 + (f >> 5)] = w4[f];
    }
    __syncthreads();

    {
        const int jo  = tid & 31;
        const int kkg = tid >> 5;
        float a1[4] = {b1[jo], b1[jo], b1[jo], b1[jo]};
        float a3[4] = {b3[jo], b3[jo], b3[jo], b3[jo]};
        #pragma unroll 8
        for (int j = 0; j < ZDIM; ++j) {
            float4 zv = *(const float4*)(zs + j * 32 + kkg * 4);
            float wa = w1sT[j * 33 + jo];
            float wb = w3sT[j * 33 + jo];
            a1[0] += wa * zv.x; a1[1] += wa * zv.y; a1[2] += wa * zv.z; a1[3] += wa * zv.w;
            a3[0] += wb * zv.x; a3[1] += wb * zv.y; a3[2] += wb * zv.z; a3[3] += wb * zv.w;
        }
        #pragma unroll
        for (int u = 0; u < 4; ++u) {
            int kk = kkg * 4 + u;
            g_h1h[(size_t)(b * K_ + k0 + kk) * HID_ + jo] =
                __float2half(fmaxf(a1[u], 0.f));
            h3s[kk * 33 + jo] = fmaxf(a3[u], 0.f);
        }
    }
    __syncthreads();

    {
        const int o  = tid & 63;
        const int kg = tid >> 6;
        float ab[8];
        float bv = b4[o];
        #pragma unroll
        for (int u = 0; u < 8; ++u) ab[u] = bv;
        #pragma unroll
        for (int j = 0; j < HID_; ++j) {
            float w = w4sT[j * 65 + o];
            #pragma unroll
            for (int u = 0; u < 8; ++u)
                ab[u] += w * h3s[(kg * 8 + u) * 33 + j];
        }
        #pragma unroll
        for (int u = 0; u < 8; ++u)
            g_bias[(size_t)(b * K_ + k0 + kg * 8 + u) * COUT + o] = ab[u];
    }
}
#define HYPER_SMEM 62720

// ---------------------------------------------------------------------------
// Kernel 2: weight-gen via mma.sync fp16 (proven R10/R11)
// ---------------------------------------------------------------------------
#define D_STR 136

__global__ __launch_bounds__(256) void wgen_kernel(
    const float* __restrict__ w2, const float* __restrict__ b2)
{
    __shared__ __align__(16) char wsm[128 * D_STR * 2];
    __half* Ah = (__half*)wsm;
    __half* Bh = (__half*)(wsm + 10240);

    const int rtile = blockIdx.x;
    const int ntile = blockIdx.y;
    const int tid  = threadIdx.x;
    const int wid  = tid >> 5;
    const int lane = tid & 31;

    const uint4* hsrc = (const uint4*)(g_h1h + (size_t)ntile * 128 * HID_);
    #pragma unroll
    for (int i = 0; i < 2; ++i) {
        int q = i * 256 + tid;
        int n = q >> 2, jq = q & 3;
        *(uint4*)&Ah[n * 40 + jq * 8] = __ldg(hsrc + q);
    }
    const float4* wsrc = (const float4*)(w2 + (size_t)rtile * 128 * HID_);
    #pragma unroll
    for (int i = 0; i < 4; ++i) {
        int q = i * 256 + tid;
        int r = q >> 3, jq = q & 7;
        float4 v = __ldg(wsrc + q);
        uint32_t p0 = h2u(__floats2half2_rn(v.x, v.y));
        uint32_t p1 = h2u(__floats2half2_rn(v.z, v.w));
        sts64(smem_u32(&Bh[r * 40 + jq * 4]), p0, p1);
    }
    __syncthreads();

    const uint32_t sbA = smem_u32(Ah);
    const uint32_t sbB = smem_u32(Bh);
    const int nb = (wid & 1) * 64;
    const int rb = (wid >> 1) * 32;

    float acc[4][4][4];
    #pragma unroll
    for (int mt = 0; mt < 4; ++mt)
        #pragma unroll
        for (int nt = 0; nt < 4; ++nt)
            #pragma unroll
            for (int u = 0; u < 4; ++u) acc[mt][nt][u] = 0.f;

    const int a_row = lane & 15;
    const int a_kh  = lane >> 4;
    const int b_row = lane & 7;
    const int b_ks  = (lane >> 3) & 1;

    #pragma unroll
    for (int ks = 0; ks < 2; ++ks) {
        const int k0 = ks * 16;
        uint32_t a[4][4];
        #pragma unroll
        for (int mt = 0; mt < 4; ++mt) {
            uint32_t addr = sbA + (nb + mt * 16 + a_row) * 80 + (k0 + a_kh * 8) * 2;
            LDSM_X4(a[mt][0], a[mt][1], a[mt][2], a[mt][3], addr);
        }
        uint32_t bf[4][2];
        #pragma unroll
        for (int nt = 0; nt < 4; ++nt) {
            uint32_t addr = sbB + (rb + nt * 8 + b_row) * 80 + (k0 + b_ks * 8) * 2;
            LDSM_X2(bf[nt][0], bf[nt][1], addr);
        }
        #pragma unroll
        for (int mt = 0; mt < 4; ++mt)
            #pragma unroll
            for (int nt = 0; nt < 4; ++nt)
                MMA16816F(acc[mt][nt], a[mt][0], a[mt][1], a[mt][2], a[mt][3],
                          bf[nt][0], bf[nt][1]);
    }

    __syncthreads();
    __half* D = (__half*)wsm;
    const int g   = lane >> 2;
    const int tig = lane & 3;
    #pragma unroll
    for (int nt = 0; nt < 4; ++nt) {
        const int rl = rb + nt * 8 + tig * 2;
        const int r  = rtile * 128 + rl;
        const float bv0 = __ldg(b2 + r);
        const float bv1 = __ldg(b2 + r + 1);
        #pragma unroll
        for (int mt = 0; mt < 4; ++mt) {
            const int n0 = nb + mt * 16 + g;
            *(__half2*)(D + n0 * D_STR + rl) =
                __floats2half2_rn(acc[mt][nt][0] + bv0, acc[mt][nt][1] + bv1);
            *(__half2*)(D + (n0 + 8) * D_STR + rl) =
                __floats2half2_rn(acc[mt][nt][2] + bv0, acc[mt][nt][3] + bv1);
        }
    }
    __syncthreads();

    #pragma unroll
    for (int i = 0; i < 8; ++i) {
        int q = i * 256 + tid;
        int row = q >> 4, col = (q & 15) * 8;
        uint4 v = *(const uint4*)(D + row * D_STR + col);
        *(uint4*)(g_weight + (size_t)(ntile * 128 + row) * RTOT + rtile * 128 + col) = v;
    }
}

// ---------------------------------------------------------------------------
// Kernel 3: main GEMM via mma.sync fp16 — R11 layout (best measured) +
// bias staged via cp.async alongside W.
// Region0 [0,18432): x fp32 staging(17408)+P(1024) -> B fp16 [c][o] 144B rows
//                    -> out fp32 staging [o][72f] 288B rows.
// Region1 [18432, 29872): A fp16 [sp][ch] 176B rows.
// Bias    [29872, 30128): 64 fp32.
// ---------------------------------------------------------------------------
#define P_OFF    17408u
#define A_OFF    18432u
#define A_STR    176
#define O_STRF   72
#define BIAS_OFF 29872u
#define SM_MAIN  30128

__global__ __launch_bounds__(128, 6) void main_mma_kernel(
    const float* __restrict__ x, float* __restrict__ out)
{
    extern __shared__ __align__(1024) char smem[];
    const uint32_t sb = smem_u32(smem);
    const int tid  = threadIdx.x;
    const int wid  = tid >> 5;
    const int lane = tid & 31;
    const int n  = (N_ - 1) - blockIdx.x;
    const int b  = n >> 10;
    const int t0 = (n & 1023) * 64;

    const float* xb = x + (size_t)b * CIN * T_ + t0;
    float* Xs = (float*)smem;                 // [ch][s], stride 68 floats
    float* P  = (float*)(smem + P_OFF);

    // phase 0: x -> staging via cp.async
    #pragma unroll
    for (int i = 0; i < 8; ++i) {
        int f = i * 128 + tid;
        int ch = f >> 4, sc = (f & 15) * 4;
        CPA16(sb + (uint32_t)(ch * 68 + sc) * 4, xb + (size_t)ch * T_ + sc);
    }
    if (tid < 64) P[tid] = t0 ? __ldg(xb + (size_t)tid * T_ - 1) : 0.f;
    CPA_COMMIT();
    CPA_WAIT0();
    __syncthreads();

    // phase 1: A-build (fp16 [sp][ch], rows 0..64)
    if (tid < 16) {
        float4 p = *(const float4*)(P + tid * 4);
        sts64(sb + A_OFF + tid * 8,
              h2u(__floats2half2_rn(p.x, p.y)), h2u(__floats2half2_rn(p.z, p.w)));
    }
    #pragma unroll
    for (int i = 0; i < 8; ++i) {
        int idx = i * 128 + tid;
        int sp  = (idx & 63) + 1;
        int chg = idx >> 6;
        const float* xs = Xs + chg * 4 * 68 + (sp - 1);
        float e0 = xs[0], e1 = xs[68], e2 = xs[136], e3 = xs[204];
        sts64(sb + A_OFF + sp * A_STR + chg * 8,
              h2u(__floats2half2_rn(e0, e1)), h2u(__floats2half2_rn(e2, e3)));
    }
    __syncthreads();   // staging fully consumed -> region0 reusable as B

    // phase 2: W -> B (region0) + bias -> smem via cp.async
    {
        const uint4* wsrc = (const uint4*)(g_weight + (size_t)n * RTOT);
        #pragma unroll
        for (int i = 0; i < 8; ++i) {
            int f4 = i * 128 + tid;
            int c = f4 >> 3, o0 = (f4 & 7) * 8;
            CPA16(sb + (uint32_t)(c * 144 + o0 * 2), wsrc + f4);
        }
        if (tid < 16)
            CPA16(sb + BIAS_OFF + tid * 16, g_bias + (size_t)n * COUT + tid * 4);
        CPA_COMMIT();
        CPA_WAIT0();
    }
    __syncthreads();

    // phase 3: MMA mainloop
    const int s_base = (wid & 1) * 32;
    const int o_base = (wid >> 1) * 32;

    float acc[2][4][4];
    #pragma unroll
    for (int mt = 0; mt < 2; ++mt)
        #pragma unroll
        for (int nt = 0; nt < 4; ++nt)
            #pragma unroll
            for (int r = 0; r < 4; ++r) acc[mt][nt][r] = 0.f;

    const uint32_t a_row = lane & 15;
    const uint32_t a_kh  = lane >> 4;
    const uint32_t b_kr  = lane & 15;

    #pragma unroll
    for (int k = 0; k < 8; ++k) {
        const int rowoff = (k < 4) ? 1 : 0;
        const int chcol  = (k & 3) * 16;
        uint32_t a[2][4];
        #pragma unroll
        for (int mt = 0; mt < 2; ++mt) {
            uint32_t addr = sb + A_OFF
                          + (rowoff + s_base + mt * 16 + a_row) * A_STR
                          + (chcol + a_kh * 8) * 2;
            LDSM_X4(a[mt][0], a[mt][1], a[mt][2], a[mt][3], addr);
        }
        uint32_t bf[4][2];
        #pragma unroll
        for (int nt = 0; nt < 4; ++nt) {
            uint32_t addr = sb + (k * 16 + b_kr) * 144 + (o_base + nt * 8) * 2;
            LDSM_X2T(bf[nt][0], bf[nt][1], addr);
        }
        #pragma unroll
        for (int mt = 0; mt < 2; ++mt)
            #pragma unroll
            for (int nt = 0; nt < 4; ++nt)
                MMA16816F(acc[mt][nt], a[mt][0], a[mt][1], a[mt][2], a[mt][3],
                          bf[nt][0], bf[nt][1]);
    }
    __syncthreads();   // all LDSM done -> region0 reusable as out staging

    // phase 4: epilogue — frags + smem bias -> smem [o][s], then coalesced stores
    {
        float* D  = (float*)smem;            // [64 o][O_STRF]
        const float* bs = (const float*)(smem + BIAS_OFF);
        const int g   = lane >> 2;
        const int tig = lane & 3;
        #pragma unroll
        for (int nt = 0; nt < 4; ++nt) {
            const int o = o_base + nt * 8 + 2 * tig;
            const float bv0 = bs[o];
            const float bv1 = bs[o + 1];
            #pragma unroll
            for (int mt = 0; mt < 2; ++mt) {
                const int s = s_base + mt * 16 + g;
                D[o * O_STRF + s]           = acc[mt][nt][0] + bv0;
                D[(o + 1) * O_STRF + s]     = acc[mt][nt][1] + bv1;
                D[o * O_STRF + s + 8]       = acc[mt][nt][2] + bv0;
                D[(o + 1) * O_STRF + s + 8] = acc[mt][nt][3] + bv1;
            }
        }
        __syncthreads();

        float* ob = out + (size_t)b * COUT * T_ + t0;
        #pragma unroll
        for (int i = 0; i < 8; ++i) {
            int q = i * 128 + tid;
            int row = q >> 4, col = (q & 15) * 4;
            float4 v = *(const float4*)(D + row * O_STRF + col);
            *(float4*)(ob + (size_t)row * T_ + col) = v;
        }
    }
}

// ---------------------------------------------------------------------------
extern "C" void kernel_launch(void* const* d_in, const int* in_sizes, int n_in,
                              void* d_out, int out_size)
{
    const float* x  = (const float*)d_in[0];
    const float* z  = (const float*)d_in[1];
    const float* w1 = (const float*)d_in[2];
    const float* b1 = (const float*)d_in[3];
    const float* w2 = (const float*)d_in[4];
    const float* b2 = (const float*)d_in[5];
    const float* w3 = (const float*)d_in[6];
    const float* b3 = (const float*)d_in[7];
    const float* w4 = (const float*)d_in[8];
    const float* b4 = (const float*)d_in[9];
    float* out = (float*)d_out;

    cudaFuncSetAttribute(hyper_kernel,    cudaFuncAttributeMaxDynamicSharedMemorySize, HYPER_SMEM);
    cudaFuncSetAttribute(main_mma_kernel, cudaFuncAttributeMaxDynamicSharedMemorySize, SM_MAIN);

    hyper_kernel<<<dim3(32, 8), 256, HYPER_SMEM>>>(z, w1, b1, w3, b3, w4, b4);
    wgen_kernel<<<dim3(64, 64), 256>>>(w2, b2);
    main_mma_kernel<<<N_, 128, SM_MAIN>>>(x, out);
}